// round 8
// baseline (speedup 1.0000x reference)
#include <cuda_runtime.h>
#include <math_constants.h>

#define HH 1024
#define WW 1024
#define NCH 48
#define RSTRIP 16
#define SLICES (HH / RSTRIP)   // 64 row-slices per channel
#define NGRP 6
#define GW (NCH / NGRP)        // 8 channels per group

// Per-(channel, row-slice) max of raw |det|. Every slot is written on every
// run by pass 1, so no init kernel and no atomics are needed.
__device__ float g_bmax[NCH * SLICES];

// det = gxx*gyy - gxy^2 reformulated:
//   t = a + c, C = a - c (a=row above, b=center, c=row below)
//   gxx+gyy = 2p,  p = t[j] + t[j+2] - 4 b[j+1]
//   gxx-gyy = 4r,  r = b[j] + b[j+2] - t[j+1]
//   gxx*gyy = p^2 - (2r)^2 ;  gxy = C[j+2] - C[j]

// ---------------------------------------------------------------------------
// Pass 1: per-slice max of raw scores. No NMS, no output stores.
// ---------------------------------------------------------------------------
__device__ __forceinline__ void ldrow10(const float* __restrict__ row, int gc,
                                        int lane, float u[10]) {
    float4 m0 = *reinterpret_cast<const float4*>(row + gc);
    float4 m1 = *reinterpret_cast<const float4*>(row + gc + 4);
    u[1] = m0.x; u[2] = m0.y; u[3] = m0.z; u[4] = m0.w;
    u[5] = m1.x; u[6] = m1.y; u[7] = m1.z; u[8] = m1.w;
    u[0] = __shfl_up_sync(0xffffffffu, u[8], 1);
    u[9] = __shfl_down_sync(0xffffffffu, u[1], 1);
    if (lane == 0)  u[0] = row[max(gc - 1, 0)];
    if (lane == 31) u[9] = row[min(gc + 8, WW - 1)];
}

__global__ __launch_bounds__(128, 8)
void max_kernel(const float* __restrict__ x, int ch0) {
    __shared__ float wmax[4];
    const int ch = ch0 + blockIdx.y;
    const int y0 = blockIdx.x * RSTRIP;
    const int gc = threadIdx.x * 8;
    const int lane = threadIdx.x & 31;
    const float* __restrict__ xc = x + (size_t)ch * (HH * WW);

    float X[3][10];
    ldrow10(xc + max(y0 - 1, 0) * WW, gc, lane, X[0]);
    ldrow10(xc + y0 * WW, gc, lane, X[1]);

    float m = 0.0f;
    #pragma unroll
    for (int i = 0; i < RSTRIP; i++) {
        const int ry = min(y0 + i + 1, HH - 1);
        ldrow10(xc + ry * WW, gc, lane, X[(i + 2) % 3]);
        const float* a = X[i % 3];
        const float* b = X[(i + 1) % 3];
        const float* c = X[(i + 2) % 3];

        float t[10], C[10];
        #pragma unroll
        for (int k = 0; k < 10; k++) { t[k] = a[k] + c[k]; C[k] = a[k] - c[k]; }

        #pragma unroll
        for (int j = 0; j < 8; j++) {
            float u = t[j] + t[j + 2];
            float p = fmaf(-4.0f, b[j + 1], u);
            float r = (b[j] + b[j + 2]) - t[j + 1];
            float r2 = r + r;
            float gxy = C[j + 2] - C[j];
            float m1 = fmaf(r2, r2, gxy * gxy);
            float det = fmaf(p, p, -m1);
            m = fmaxf(m, fabsf(det));
        }
    }

    #pragma unroll
    for (int off = 16; off > 0; off >>= 1)
        m = fmaxf(m, __shfl_xor_sync(0xffffffffu, m, off));
    if (lane == 0) wmax[threadIdx.x >> 5] = m;
    __syncthreads();
    if (threadIdx.x == 0) {
        m = fmaxf(fmaxf(wmax[0], wmax[1]), fmaxf(wmax[2], wmax[3]));
        g_bmax[ch * SLICES + blockIdx.x] = m;
    }
}

// ---------------------------------------------------------------------------
// Pass 2: scores + separable NMS + normalization, registers only.
// ---------------------------------------------------------------------------
__device__ __forceinline__ void ldrow8(const float* __restrict__ row, int gc,
                                       int lane, int lcm2, int lcm1,
                                       int lcp4, int lcp5, float v[8]) {
    float4 m = *reinterpret_cast<const float4*>(row + gc);
    v[2] = m.x; v[3] = m.y; v[4] = m.z; v[5] = m.w;
    v[0] = __shfl_up_sync(0xffffffffu, v[4], 1);
    v[1] = __shfl_up_sync(0xffffffffu, v[5], 1);
    v[6] = __shfl_down_sync(0xffffffffu, v[2], 1);
    v[7] = __shfl_down_sync(0xffffffffu, v[3], 1);
    if (lane == 0)  { v[0] = row[lcm2]; v[1] = row[lcm1]; }
    if (lane == 31) { v[6] = row[lcp4]; v[7] = row[lcp5]; }
}

__global__ __launch_bounds__(256, 6)
void hessian_kernel(const float* __restrict__ x, float* __restrict__ out, int ch0) {
    __shared__ float redsm[2];
    const int ch = ch0 + blockIdx.y;
    const int y0 = blockIdx.x * RSTRIP;
    const int gc = threadIdx.x * 4;
    const int lane = threadIdx.x & 31;
    const float* __restrict__ xc = x + (size_t)ch * (HH * WW);
    float* __restrict__ oc = out + (size_t)ch * (HH * WW);

    // Reduce the 64 per-slice maxima for this channel (L2-hit loads).
    if (threadIdx.x < SLICES) {
        float v = g_bmax[ch * SLICES + threadIdx.x];
        #pragma unroll
        for (int off = 16; off > 0; off >>= 1)
            v = fmaxf(v, __shfl_xor_sync(0xffffffffu, v, off));
        if ((threadIdx.x & 31) == 0) redsm[threadIdx.x >> 5] = v;
    }
    __syncthreads();
    const float inv = 1.0f / fmaxf(fmaxf(redsm[0], redsm[1]), 1e-6f);

    const int lcm2 = max(gc - 2, 0), lcm1 = max(gc - 1, 0);
    const int lcp4 = min(gc + 4, WW - 1), lcp5 = min(gc + 5, WW - 1);

    float X[3][8];                 // x rows, cols gc-2..gc+5
    float s1[6], s2[6];            // previous two score rows (cols gc-1..gc+4)
    #pragma unroll
    for (int k = 0; k < 6; k++) { s1[k] = 0.0f; s2[k] = 0.0f; }

    ldrow8(xc + max(y0 - 2, 0) * WW, gc, lane, lcm2, lcm1, lcp4, lcp5, X[0]);
    ldrow8(xc + max(y0 - 1, 0) * WW, gc, lane, lcm2, lcm1, lcp4, lcp5, X[1]);

    #pragma unroll
    for (int i = 0; i < RSTRIP + 2; i++) {
        const int sr = y0 - 1 + i;                  // score row produced this iter
        const int ry = min(y0 + i, HH - 1);
        ldrow8(xc + ry * WW, gc, lane, lcm2, lcm1, lcp4, lcp5, X[(2 + i) % 3]);
        const float* a = X[i % 3];
        const float* b = X[(i + 1) % 3];
        const float* c = X[(i + 2) % 3];

        float t[8], C[8];
        #pragma unroll
        for (int k = 0; k < 8; k++) { t[k] = a[k] + c[k]; C[k] = a[k] - c[k]; }

        float sc6[6];
        #pragma unroll
        for (int j = 0; j < 6; j++) {               // score cols gc-1+j
            float u = t[j] + t[j + 2];
            float p = fmaf(-4.0f, b[j + 1], u);
            float r = (b[j] + b[j + 2]) - t[j + 1];
            float r2 = r + r;
            float gxy = C[j + 2] - C[j];
            float m1 = fmaf(r2, r2, gxy * gxy);
            float det = fmaf(p, p, -m1);
            sc6[j] = fmaxf(fabsf(det), 1e-6f);
        }
        // Column edges: score col -1 (thread 0) / col 1024 (thread 255).
        if (gc == 0)       sc6[0] = -CUDART_INF_F;
        if (gc == WW - 4)  sc6[5] = -CUDART_INF_F;
        // Row edges: only possible at unrolled iters 0 and RSTRIP+1.
        if ((i == 0 && sr < 0) || (i == RSTRIP + 1 && sr >= HH)) {
            #pragma unroll
            for (int k = 0; k < 6; k++) sc6[k] = -CUDART_INF_F;
        }

        if (i >= 2) {
            const int y = sr - 1;                   // output row
            float cm[6];
            #pragma unroll
            for (int k = 0; k < 6; k++)
                cm[k] = fmaxf(fmaxf(s2[k], s1[k]), sc6[k]);
            float ov[4];
            #pragma unroll
            for (int k = 0; k < 4; k++) {
                float pmax = fmaxf(fmaxf(cm[k], cm[k + 1]), cm[k + 2]);
                float sv = s1[k + 1];
                ov[k] = (sv == pmax) ? sv * inv : 0.0f;
            }
            float4 o; o.x = ov[0]; o.y = ov[1]; o.z = ov[2]; o.w = ov[3];
            *reinterpret_cast<float4*>(oc + (size_t)y * WW + gc) = o;
        }

        #pragma unroll
        for (int k = 0; k < 6; k++) { s2[k] = s1[k]; s1[k] = sc6[k]; }
    }
}

extern "C" void kernel_launch(void* const* d_in, const int* in_sizes, int n_in,
                              void* d_out, int out_size) {
    const float* x = (const float*)d_in[0];
    float* out = (float*)d_out;

    // One-time resources (created on the uncaptured correctness call).
    static cudaStream_t s1 = nullptr;
    static cudaEvent_t evfork = nullptr;
    static cudaEvent_t evm[NGRP] = {};
    if (s1 == nullptr) {
        cudaStreamCreateWithFlags(&s1, cudaStreamNonBlocking);
        cudaEventCreateWithFlags(&evfork, cudaEventDisableTiming);
        for (int g = 0; g < NGRP; g++)
            cudaEventCreateWithFlags(&evm[g], cudaEventDisableTiming);
    }

    // Fork side stream from the launch/capture stream.
    cudaEventRecord(evfork, 0);
    cudaStreamWaitEvent(s1, evfork, 0);

    // Side stream: per-group channel-max passes, back-to-back.
    dim3 mgrd(SLICES, GW);
    for (int g = 0; g < NGRP; g++) {
        max_kernel<<<mgrd, 128, 0, s1>>>(x, g * GW);
        cudaEventRecord(evm[g], s1);
    }

    // Main stream: hessian(g) gated only on max(g). The wait on evm[NGRP-1]
    // also joins s1 back before the capture ends.
    dim3 hgrd(HH / RSTRIP, GW);
    for (int g = 0; g < NGRP; g++) {
        cudaStreamWaitEvent(0, evm[g], 0);
        hessian_kernel<<<hgrd, 256>>>(x, out, g * GW);
    }
}

// round 9
// speedup vs baseline: 1.1025x; 1.1025x over previous
#include <cuda_runtime.h>
#include <math_constants.h>

#define HH 1024
#define WW 1024
#define NCH 48
#define RSTRIP 16
#define SLICES (HH / RSTRIP)     // 64 row-slices per channel
#define MAXBLKS (NCH * SLICES)   // 3072 producer blocks

// Reset each replay by reset_kernel (graph-serialized before the fused kernel).
__device__ int g_smax_bits[NCH];   // channel max of clamped score, float bits
__device__ int g_done[NCH];        // producer blocks finished per channel

__global__ void reset_kernel() {
    if (threadIdx.x < NCH) {
        g_smax_bits[threadIdx.x] = __float_as_int(1e-6f);
        g_done[threadIdx.x] = 0;
    }
}

// det = gxx*gyy - gxy^2 reformulated:
//   t = a + c, C = a - c (a=row above, b=center, c=row below)
//   p = t[j] + t[j+2] - 4 b[j+1] ; r = b[j] + b[j+2] - t[j+1]
//   det = p^2 - (2r)^2 - gxy^2 ;  gxy = C[j+2] - C[j]

// 6-wide x row (cols gc-1..gc+4): 1 float4 + 2 lane shuffles.
__device__ __forceinline__ void ldrow6(const float* __restrict__ row, int gc,
                                       int lane, float v[6]) {
    float4 m = *reinterpret_cast<const float4*>(row + gc);
    v[1] = m.x; v[2] = m.y; v[3] = m.z; v[4] = m.w;
    v[0] = __shfl_up_sync(0xffffffffu, v[4], 1);   // prev lane's gc+3 == our gc-1
    v[5] = __shfl_down_sync(0xffffffffu, v[1], 1); // next lane's gc   == our gc+4
    if (lane == 0)  v[0] = row[max(gc - 1, 0)];
    if (lane == 31) v[5] = row[min(gc + 4, WW - 1)];
}

// 8-wide x row (cols gc-2..gc+5): 1 float4 + 4 lane shuffles.
__device__ __forceinline__ void ldrow8(const float* __restrict__ row, int gc,
                                       int lane, int lcm2, int lcm1,
                                       int lcp4, int lcp5, float v[8]) {
    float4 m = *reinterpret_cast<const float4*>(row + gc);
    v[2] = m.x; v[3] = m.y; v[4] = m.z; v[5] = m.w;
    v[0] = __shfl_up_sync(0xffffffffu, v[4], 1);
    v[1] = __shfl_up_sync(0xffffffffu, v[5], 1);
    v[6] = __shfl_down_sync(0xffffffffu, v[2], 1);
    v[7] = __shfl_down_sync(0xffffffffu, v[3], 1);
    if (lane == 0)  { v[0] = row[lcm2]; v[1] = row[lcm1]; }
    if (lane == 31) { v[6] = row[lcp4]; v[7] = row[lcp5]; }
}

__device__ void max_phase(const float* __restrict__ x, int w) {
    __shared__ float wmax[8];
    const int ch = w >> 6;
    const int y0 = (w & 63) * RSTRIP;
    const int gc = threadIdx.x * 4;
    const int lane = threadIdx.x & 31;
    const float* __restrict__ xc = x + (size_t)ch * (HH * WW);

    float X[3][6];
    ldrow6(xc + max(y0 - 1, 0) * WW, gc, lane, X[0]);
    ldrow6(xc + y0 * WW, gc, lane, X[1]);

    float m = 0.0f;
    #pragma unroll
    for (int i = 0; i < RSTRIP; i++) {
        const int ry = min(y0 + i + 1, HH - 1);
        ldrow6(xc + ry * WW, gc, lane, X[(i + 2) % 3]);
        const float* a = X[i % 3];
        const float* b = X[(i + 1) % 3];
        const float* c = X[(i + 2) % 3];

        float t[6], C[6];
        #pragma unroll
        for (int k = 0; k < 6; k++) { t[k] = a[k] + c[k]; C[k] = a[k] - c[k]; }

        #pragma unroll
        for (int j = 0; j < 4; j++) {               // score cols gc..gc+3
            float u = t[j] + t[j + 2];
            float p = fmaf(-4.0f, b[j + 1], u);
            float r = (b[j] + b[j + 2]) - t[j + 1];
            float r2 = r + r;
            float gxy = C[j + 2] - C[j];
            float m1 = fmaf(r2, r2, gxy * gxy);
            float det = fmaf(p, p, -m1);
            m = fmaxf(m, fabsf(det));
        }
    }

    #pragma unroll
    for (int off = 16; off > 0; off >>= 1)
        m = fmaxf(m, __shfl_xor_sync(0xffffffffu, m, off));
    if (lane == 0) wmax[threadIdx.x >> 5] = m;
    __syncthreads();
    if (threadIdx.x == 0) {
        #pragma unroll
        for (int k = 1; k < 8; k++) m = fmaxf(m, wmax[k]);
        atomicMax(&g_smax_bits[ch], __float_as_int(m));
        __threadfence();
        atomicAdd(&g_done[ch], 1);
    }
}

__device__ void hessian_phase(const float* __restrict__ x,
                              float* __restrict__ out, int w) {
    __shared__ float redsm;
    const int ch = w >> 6;
    const int y0 = (w & 63) * RSTRIP;
    const int gc = threadIdx.x * 4;
    const int lane = threadIdx.x & 31;
    const float* __restrict__ xc = x + (size_t)ch * (HH * WW);
    float* __restrict__ oc = out + (size_t)ch * (HH * WW);

    // Wait for this channel's producers (bid-ordered schedule => rarely spins).
    if (threadIdx.x == 0) {
        while (atomicAdd(&g_done[ch], 0) < SLICES) {}
        redsm = __int_as_float(atomicAdd(&g_smax_bits[ch], 0));
    }
    __syncthreads();
    const float inv = 1.0f / redsm;

    const int lcm2 = max(gc - 2, 0), lcm1 = max(gc - 1, 0);
    const int lcp4 = min(gc + 4, WW - 1), lcp5 = min(gc + 5, WW - 1);

    float X[3][8];                 // x rows, cols gc-2..gc+5
    float s1[6], s2[6];            // previous two score rows (cols gc-1..gc+4)
    #pragma unroll
    for (int k = 0; k < 6; k++) { s1[k] = 0.0f; s2[k] = 0.0f; }

    ldrow8(xc + max(y0 - 2, 0) * WW, gc, lane, lcm2, lcm1, lcp4, lcp5, X[0]);
    ldrow8(xc + max(y0 - 1, 0) * WW, gc, lane, lcm2, lcm1, lcp4, lcp5, X[1]);

    #pragma unroll
    for (int i = 0; i < RSTRIP + 2; i++) {
        const int sr = y0 - 1 + i;                  // score row produced this iter
        const int ry = min(y0 + i, HH - 1);
        ldrow8(xc + ry * WW, gc, lane, lcm2, lcm1, lcp4, lcp5, X[(2 + i) % 3]);
        const float* a = X[i % 3];
        const float* b = X[(i + 1) % 3];
        const float* c = X[(i + 2) % 3];

        float t[8], C[8];
        #pragma unroll
        for (int k = 0; k < 8; k++) { t[k] = a[k] + c[k]; C[k] = a[k] - c[k]; }

        float sc6[6];
        #pragma unroll
        for (int j = 0; j < 6; j++) {               // score cols gc-1+j
            float u = t[j] + t[j + 2];
            float p = fmaf(-4.0f, b[j + 1], u);
            float r = (b[j] + b[j + 2]) - t[j + 1];
            float r2 = r + r;
            float gxy = C[j + 2] - C[j];
            float m1 = fmaf(r2, r2, gxy * gxy);
            float det = fmaf(p, p, -m1);
            sc6[j] = fmaxf(fabsf(det), 1e-6f);
        }
        // Column edges: score col -1 (thread 0) / col 1024 (thread 255).
        if (gc == 0)       sc6[0] = -CUDART_INF_F;
        if (gc == WW - 4)  sc6[5] = -CUDART_INF_F;
        // Row edges: only possible at unrolled iters 0 and RSTRIP+1.
        if ((i == 0 && sr < 0) || (i == RSTRIP + 1 && sr >= HH)) {
            #pragma unroll
            for (int k = 0; k < 6; k++) sc6[k] = -CUDART_INF_F;
        }

        if (i >= 2) {
            const int y = sr - 1;                   // output row
            float cm[6];
            #pragma unroll
            for (int k = 0; k < 6; k++)
                cm[k] = fmaxf(fmaxf(s2[k], s1[k]), sc6[k]);
            float ov[4];
            #pragma unroll
            for (int k = 0; k < 4; k++) {
                float pmax = fmaxf(fmaxf(cm[k], cm[k + 1]), cm[k + 2]);
                float sv = s1[k + 1];
                ov[k] = (sv == pmax) ? sv * inv : 0.0f;
            }
            float4 o; o.x = ov[0]; o.y = ov[1]; o.z = ov[2]; o.w = ov[3];
            *reinterpret_cast<float4*>(oc + (size_t)y * WW + gc) = o;
        }

        #pragma unroll
        for (int k = 0; k < 6; k++) { s2[k] = s1[k]; s1[k] = sc6[k]; }
    }
}

// Producers (bids 0..MAXBLKS-1) strictly precede consumers in bid order;
// producers never block, so consumer spins cannot deadlock.
__global__ __launch_bounds__(256, 6)
void fused_kernel(const float* __restrict__ x, float* __restrict__ out) {
    const int bid = blockIdx.x;
    if (bid < MAXBLKS) max_phase(x, bid);
    else               hessian_phase(x, out, bid - MAXBLKS);
}

extern "C" void kernel_launch(void* const* d_in, const int* in_sizes, int n_in,
                              void* d_out, int out_size) {
    const float* x = (const float*)d_in[0];
    float* out = (float*)d_out;

    reset_kernel<<<1, 64>>>();
    fused_kernel<<<2 * MAXBLKS, 256>>>(x, out);
}